// round 4
// baseline (speedup 1.0000x reference)
#include <cuda_runtime.h>

#define NT   512
#define TT   512
#define RQ   65      // row stride (in float2) for interleaved xkq tile

__global__ __launch_bounds__(NT, 1)
void ttt_kernel(const float* __restrict__ XQ, const float* __restrict__ XK,
                const float* __restrict__ XV, const float* __restrict__ W1,
                const float* __restrict__ b1, const float* __restrict__ gam,
                const float* __restrict__ bet, float* __restrict__ out)
{
    __shared__ float  W[4096];          // W[d*64+f], carried across steps
    __shared__ float2 xkq[16*RQ];       // xkq[k*RQ+d] = (xk[k][d], xq[k][d])
    __shared__ float2 gz_s[16*32];      // gz[k][f] as float2, row stride 32
    __shared__ float  bb[64];           // carried bias
    __shared__ float  eta_s[16];

    const int tid = threadIdx.x;
    const int bh  = blockIdx.x;
    const int h   = bh & 15;
    const int k   = tid >> 5;           // warp = token row 0..15
    const int q2  = tid & 31;           // lane: 2 features
    const int f0  = q2 << 1;
    const int kp  = q2 & 15;            // A column this lane owns

    const size_t base = (size_t)bh * (TT * 1024);
    const float* xqg = XQ + base;
    const float* xkg = XK + base;
    const float* xvg = XV + base;
    float*       og  = out + base;

    // ---- init carried state ----
    {
        const float* Wg = W1 + (size_t)h * 4096;
        #pragma unroll
        for (int i = 0; i < 2; i++)
            *(float4*)&W[i*2048 + tid*4] = *(const float4*)&Wg[i*2048 + tid*4];
        if (tid < 16)
            *(float4*)&bb[tid*4] = *(const float4*)&b1[h*64 + tid*4];
    }
    const float2 g2  = *(const float2*)&gam[h*64 + f0];
    const float2 be2 = *(const float2*)&bet[h*64 + f0];
    float2* Wv = (float2*)W;            // Wv[d*32 + q2]

    // prefetch tiles for t=0 (tid*2 == k*64 + f0)
    float2 q4 = *(const float2*)&xqg[tid*2];
    float2 k4 = *(const float2*)&xkg[tid*2];
    float2 v4 = *(const float2*)&xvg[tid*2];

    for (int t = 0; t < TT; t++) {
        // ---- stage interleaved tile + eta ----
        xkq[k*RQ + f0    ] = make_float2(k4.x, q4.x);
        xkq[k*RQ + f0 + 1] = make_float2(k4.y, q4.y);

        float ss = k4.x*k4.x + k4.y*k4.y;
        #pragma unroll
        for (int m = 16; m >= 1; m >>= 1)
            ss += __shfl_xor_sync(~0u, ss, m);
        if (q2 == 0) eta_s[k] = 0.01f / (1.0f + fmaxf(sqrtf(ss), 1e-6f));
        __syncthreads();                                   // S1

        // ---- prefetch next step's tiles (hide DRAM under compute) ----
        float2 nq4 = make_float2(0.f,0.f), nk4 = nq4, nv4 = nq4;
        if (t + 1 < TT) {
            const size_t off = (size_t)(t+1)*1024 + tid*2;
            nq4 = *(const float2*)&xqg[off];
            nk4 = *(const float2*)&xkg[off];
            nv4 = *(const float2*)&xvg[off];
        }

        // em = mean(eta), el = eta[15]
        float em, el;
        {
            const float4 e0 = *(const float4*)&eta_s[0];
            const float4 e1 = *(const float4*)&eta_s[4];
            const float4 e2 = *(const float4*)&eta_s[8];
            const float4 e3 = *(const float4*)&eta_s[12];
            em = ((e0.x+e0.y+e0.z+e0.w) + (e1.x+e1.y+e1.z+e1.w)
                + (e2.x+e2.y+e2.z+e2.w) + (e3.x+e3.y+e3.z+e3.w)) * (1.0f/16.0f);
            el = e3.w;
        }

        // ---- fused: z=xk@W+b, zd=xq@W+b, a=xq[k].xk[kp]+1 (shared loads) ----
        float2 z  = *(const float2*)&bb[f0];
        float2 zd = z;
        float  a  = 1.0f;
        #pragma unroll 8
        for (int d = 0; d < 64; d++) {
            const float2 kq  = xkq[k*RQ + d];       // (xk[k][d], xq[k][d]) bcast
            const float  xkp = xkq[kp*RQ + d].x;    // xk[kp][d], conflict-free
            const float2 w   = Wv[d*32 + q2];
            z.x  = fmaf(kq.x, w.x, z.x);   z.y  = fmaf(kq.x, w.y, z.y);
            zd.x = fmaf(kq.y, w.x, zd.x);  zd.y = fmaf(kq.y, w.y, zd.y);
            a    = fmaf(kq.y, xkp, a);
        }

        // ---- LN(z) single-pass -> grad_Z1 ----
        float s1 = z.x + z.y;
        float s2 = z.x*z.x + z.y*z.y;
        #pragma unroll
        for (int m = 16; m >= 1; m >>= 1) {
            s1 += __shfl_xor_sync(~0u, s1, m);
            s2 += __shfl_xor_sync(~0u, s2, m);
        }
        const float mu  = s1 * 0.015625f;
        const float var = fmaf(-mu, mu, s2 * 0.015625f);
        const float r   = rsqrtf(var + 1e-6f);
        float2 gz;
        gz.x = 2.0f * (fmaf(g2.x, (z.x-mu)*r, be2.x) - v4.x + k4.x);
        gz.y = 2.0f * (fmaf(g2.y, (z.y-mu)*r, be2.y) - v4.y + k4.y);
        gz_s[k*32 + q2] = gz;
        __syncthreads();                                   // S2

        // ---- carry update: rank-1, in place (no W reads until next step) ----
        {
            const float2 gl = gz_s[15*32 + q2];
            #pragma unroll
            for (int j = 0; j < 4; j++) {
                const int d = k + 16*j;
                const float cf = -el * xkq[15*RQ + d].x;
                float2 w = Wv[d*32 + q2];
                w.x = fmaf(cf, gl.x, w.x); w.y = fmaf(cf, gl.y, w.y);
                Wv[d*32 + q2] = w;
            }
            if (k == 0) {   // warp 0 updates bias
                float2 bv = *(float2*)&bb[f0];
                bv.x = fmaf(-el, gl.x, bv.x); bv.y = fmaf(-el, gl.y, bv.y);
                *(float2*)&bb[f0] = bv;
            }
        }

        // ---- correction: zd -= em * (A' @ gz), A' broadcast from registers ----
        float2 c = make_float2(0.f, 0.f);
        #pragma unroll
        for (int j = 0; j < 16; j++) {
            const float av  = __shfl_sync(~0u, a, j);
            const float2 gv = gz_s[j*32 + q2];
            c.x = fmaf(av, gv.x, c.x); c.y = fmaf(av, gv.y, c.y);
        }
        zd.x = fmaf(-em, c.x, zd.x); zd.y = fmaf(-em, c.y, zd.y);

        // ---- LN(zd) single-pass, out = xq + ln ----
        float t1 = zd.x + zd.y;
        float t2 = zd.x*zd.x + zd.y*zd.y;
        #pragma unroll
        for (int m = 16; m >= 1; m >>= 1) {
            t1 += __shfl_xor_sync(~0u, t1, m);
            t2 += __shfl_xor_sync(~0u, t2, m);
        }
        const float mu2  = t1 * 0.015625f;
        const float var2 = fmaf(-mu2, mu2, t2 * 0.015625f);
        const float r2   = rsqrtf(var2 + 1e-6f);
        float2 o;
        o.x = q4.x + fmaf(g2.x, (zd.x-mu2)*r2, be2.x);
        o.y = q4.y + fmaf(g2.y, (zd.y-mu2)*r2, be2.y);
        *(float2*)&og[(size_t)t*1024 + tid*2] = o;

        __syncthreads();                                   // S3 (readers done, W update visible)

        q4 = nq4; k4 = nk4; v4 = nv4;
    }
}

extern "C" void kernel_launch(void* const* d_in, const int* in_sizes, int n_in,
                              void* d_out, int out_size) {
    const float* XQ  = (const float*)d_in[0];
    const float* XK  = (const float*)d_in[1];
    const float* XV  = (const float*)d_in[2];
    const float* W1  = (const float*)d_in[3];
    const float* b1  = (const float*)d_in[4];
    const float* gam = (const float*)d_in[5];
    const float* bet = (const float*)d_in[6];
    float* out = (float*)d_out;

    const int nbh = in_sizes[0] / (TT * 16 * 64);   // B*H = 64
    ttt_kernel<<<nbh, NT>>>(XQ, XK, XV, W1, b1, gam, bet, out);
}

// round 5
// speedup vs baseline: 1.2872x; 1.2872x over previous
#include <cuda_runtime.h>

#define NT   256
#define TT   512
#define ROWP 68      // padded row stride (floats) for 16x64 tiles

__global__ __launch_bounds__(NT, 1)
void ttt_kernel(const float* __restrict__ XQ, const float* __restrict__ XK,
                const float* __restrict__ XV, const float* __restrict__ W1,
                const float* __restrict__ b1, const float* __restrict__ gam,
                const float* __restrict__ bet, float* __restrict__ out)
{
    __shared__ float W[4096];            // W[d*64+f], carried
    __shared__ float xq_s[2][16*ROWP];   // double-buffered tiles
    __shared__ float xk_s[2][16*ROWP];
    __shared__ float gz_s[16*ROWP];
    __shared__ float bb[64];             // carried bias
    __shared__ float eta_s[2][16];

    const int tid = threadIdx.x;
    const int bh  = blockIdx.x;
    const int h   = bh & 15;
    const int k   = tid >> 4;            // token row 0..15
    const int q   = tid & 15;
    const int f0  = q << 2;              // 4 features per thread

    const size_t base = (size_t)bh * (TT * 1024);
    const float* xqg = XQ + base;
    const float* xkg = XK + base;
    const float* xvg = XV + base;
    float*       og  = out + base;

    // ---- init carried state ----
    {
        const float* Wg = W1 + (size_t)h * 4096;
        #pragma unroll
        for (int i = 0; i < 4; i++)
            *(float4*)&W[i*1024 + tid*4] = *(const float4*)&Wg[i*1024 + tid*4];
        if (tid < 16)
            *(float4*)&bb[tid*4] = *(const float4*)&b1[h*64 + tid*4];
    }
    const float4 g4  = *(const float4*)&gam[h*64 + f0];
    const float4 be4 = *(const float4*)&bet[h*64 + f0];

    // ---- stage step 0 tiles + eta0 into buffer 0 ----
    float4 q4 = *(const float4*)&xqg[tid*4];
    float4 k4 = *(const float4*)&xkg[tid*4];
    float4 v4 = *(const float4*)&xvg[tid*4];
    *(float4*)&xq_s[0][k*ROWP + f0] = q4;
    *(float4*)&xk_s[0][k*ROWP + f0] = k4;
    {
        float ss = k4.x*k4.x + k4.y*k4.y + k4.z*k4.z + k4.w*k4.w;
        #pragma unroll
        for (int m = 8; m >= 1; m >>= 1) ss += __shfl_xor_sync(~0u, ss, m, 16);
        if (q == 0) eta_s[0][k] = 0.01f / (1.0f + fmaxf(sqrtf(ss), 1e-6f));
    }
    __syncthreads();

    int p = 0;
    for (int t = 0; t < TT; t++) {
        // ---- prefetch next step's tiles early (hide DRAM) ----
        float4 nq4 = make_float4(0.f,0.f,0.f,0.f), nk4 = nq4, nv4 = nq4;
        if (t + 1 < TT) {
            const size_t off = (size_t)(t+1)*1024 + tid*4;
            nq4 = *(const float4*)&xqg[off];
            nk4 = *(const float4*)&xkg[off];
            nv4 = *(const float4*)&xvg[off];
        }

        // em = mean(eta), el = eta[15] (plain smem reads, precomputed)
        float em, el;
        {
            const float4 e0 = *(const float4*)&eta_s[p][0];
            const float4 e1 = *(const float4*)&eta_s[p][4];
            const float4 e2 = *(const float4*)&eta_s[p][8];
            const float4 e3 = *(const float4*)&eta_s[p][12];
            em = ((e0.x+e0.y+e0.z+e0.w) + (e1.x+e1.y+e1.z+e1.w)
                + (e2.x+e2.y+e2.z+e2.w) + (e3.x+e3.y+e3.z+e3.w)) * (1.0f/16.0f);
            el = e3.w;
        }

        // ---- fused: z=xk@W+b, zd=xq@W+b, a=xq[k].xk[q]+1 ----
        const float* xqp = &xq_s[p][0];
        const float* xkp = &xk_s[p][0];
        float4 z  = *(const float4*)&bb[f0];
        float4 zd = z;
        float  a  = 1.0f;
        #pragma unroll 4
        for (int j = 0; j < 16; j++) {
            const int d0 = j << 2;
            const float4 xk4 = *(const float4*)&xkp[k*ROWP + d0];
            const float4 xq4 = *(const float4*)&xqp[k*ROWP + d0];
            const float4 xkA = *(const float4*)&xkp[q*ROWP + d0];
            a = fmaf(xq4.x, xkA.x, a);
            a = fmaf(xq4.y, xkA.y, a);
            a = fmaf(xq4.z, xkA.z, a);
            a = fmaf(xq4.w, xkA.w, a);
            {
                const float4 w = *(const float4*)&W[(d0+0)*64 + f0];
                z.x  = fmaf(xk4.x, w.x, z.x);  z.y  = fmaf(xk4.x, w.y, z.y);
                z.z  = fmaf(xk4.x, w.z, z.z);  z.w  = fmaf(xk4.x, w.w, z.w);
                zd.x = fmaf(xq4.x, w.x, zd.x); zd.y = fmaf(xq4.x, w.y, zd.y);
                zd.z = fmaf(xq4.x, w.z, zd.z); zd.w = fmaf(xq4.x, w.w, zd.w);
            }
            {
                const float4 w = *(const float4*)&W[(d0+1)*64 + f0];
                z.x  = fmaf(xk4.y, w.x, z.x);  z.y  = fmaf(xk4.y, w.y, z.y);
                z.z  = fmaf(xk4.y, w.z, z.z);  z.w  = fmaf(xk4.y, w.w, z.w);
                zd.x = fmaf(xq4.y, w.x, zd.x); zd.y = fmaf(xq4.y, w.y, zd.y);
                zd.z = fmaf(xq4.y, w.z, zd.z); zd.w = fmaf(xq4.y, w.w, zd.w);
            }
            {
                const float4 w = *(const float4*)&W[(d0+2)*64 + f0];
                z.x  = fmaf(xk4.z, w.x, z.x);  z.y  = fmaf(xk4.z, w.y, z.y);
                z.z  = fmaf(xk4.z, w.z, z.z);  z.w  = fmaf(xk4.z, w.w, z.w);
                zd.x = fmaf(xq4.z, w.x, zd.x); zd.y = fmaf(xq4.z, w.y, zd.y);
                zd.z = fmaf(xq4.z, w.z, zd.z); zd.w = fmaf(xq4.z, w.w, zd.w);
            }
            {
                const float4 w = *(const float4*)&W[(d0+3)*64 + f0];
                z.x  = fmaf(xk4.w, w.x, z.x);  z.y  = fmaf(xk4.w, w.y, z.y);
                z.z  = fmaf(xk4.w, w.z, z.z);  z.w  = fmaf(xk4.w, w.w, z.w);
                zd.x = fmaf(xq4.w, w.x, zd.x); zd.y = fmaf(xq4.w, w.y, zd.y);
                zd.z = fmaf(xq4.w, w.z, zd.z); zd.w = fmaf(xq4.w, w.w, zd.w);
            }
        }

        // ---- LN(z) single-pass -> grad_Z1 ----
        float s1 = z.x + z.y + z.z + z.w;
        float s2 = z.x*z.x + z.y*z.y + z.z*z.z + z.w*z.w;
        #pragma unroll
        for (int m = 8; m >= 1; m >>= 1) {
            s1 += __shfl_xor_sync(~0u, s1, m, 16);
            s2 += __shfl_xor_sync(~0u, s2, m, 16);
        }
        const float mu  = s1 * 0.015625f;
        const float var = fmaf(-mu, mu, s2 * 0.015625f);
        const float r   = rsqrtf(var + 1e-6f);
        float4 gz;
        gz.x = 2.0f * (fmaf(g4.x, (z.x-mu)*r, be4.x) - v4.x + k4.x);
        gz.y = 2.0f * (fmaf(g4.y, (z.y-mu)*r, be4.y) - v4.y + k4.y);
        gz.z = 2.0f * (fmaf(g4.z, (z.z-mu)*r, be4.z) - v4.z + k4.z);
        gz.w = 2.0f * (fmaf(g4.w, (z.w-mu)*r, be4.w) - v4.w + k4.w);
        *(float4*)&gz_s[k*ROWP + f0] = gz;
        __syncthreads();                                   // S2

        // ---- carry update: rank-1, in place ----
        {
            const float4 gl = *(const float4*)&gz_s[15*ROWP + f0];
            #pragma unroll
            for (int j = 0; j < 4; j++) {
                const int d = k + 16*j;
                const float cf = -el * xkp[15*ROWP + d];
                float4 w4 = *(float4*)&W[d*64 + f0];
                w4.x = fmaf(cf, gl.x, w4.x); w4.y = fmaf(cf, gl.y, w4.y);
                w4.z = fmaf(cf, gl.z, w4.z); w4.w = fmaf(cf, gl.w, w4.w);
                *(float4*)&W[d*64 + f0] = w4;
            }
            if (tid < 16) {   // k==0, f0 == tid*4, gl == gz_s[15][f0]
                float4 bv = *(float4*)&bb[f0];
                bv.x = fmaf(-el, gl.x, bv.x); bv.y = fmaf(-el, gl.y, bv.y);
                bv.z = fmaf(-el, gl.z, bv.z); bv.w = fmaf(-el, gl.w, bv.w);
                *(float4*)&bb[f0] = bv;
            }
        }

        // ---- correction: zd -= em * (A' @ gz), A' via half-warp shfl ----
        float4 c = make_float4(0.f,0.f,0.f,0.f);
        #pragma unroll
        for (int kp2 = 0; kp2 < 16; kp2++) {
            const float av  = __shfl_sync(~0u, a, kp2, 16);
            const float4 gv = *(const float4*)&gz_s[kp2*ROWP + f0];
            c.x = fmaf(av, gv.x, c.x); c.y = fmaf(av, gv.y, c.y);
            c.z = fmaf(av, gv.z, c.z); c.w = fmaf(av, gv.w, c.w);
        }
        zd.x = fmaf(-em, c.x, zd.x); zd.y = fmaf(-em, c.y, zd.y);
        zd.z = fmaf(-em, c.z, zd.z); zd.w = fmaf(-em, c.w, zd.w);

        // ---- LN(zd) single-pass, out = xq + ln ----
        float t1 = zd.x + zd.y + zd.z + zd.w;
        float t2 = zd.x*zd.x + zd.y*zd.y + zd.z*zd.z + zd.w*zd.w;
        #pragma unroll
        for (int m = 8; m >= 1; m >>= 1) {
            t1 += __shfl_xor_sync(~0u, t1, m, 16);
            t2 += __shfl_xor_sync(~0u, t2, m, 16);
        }
        const float mu2  = t1 * 0.015625f;
        const float var2 = fmaf(-mu2, mu2, t2 * 0.015625f);
        const float r2   = rsqrtf(var2 + 1e-6f);
        float4 o;
        o.x = q4.x + fmaf(g4.x, (zd.x-mu2)*r2, be4.x);
        o.y = q4.y + fmaf(g4.y, (zd.y-mu2)*r2, be4.y);
        o.z = q4.z + fmaf(g4.z, (zd.z-mu2)*r2, be4.z);
        o.w = q4.w + fmaf(g4.w, (zd.w-mu2)*r2, be4.w);
        *(float4*)&og[(size_t)t*1024 + tid*4] = o;

        // ---- stage NEXT step's tiles + eta into other buffer ----
        const int pn = p ^ 1;
        *(float4*)&xq_s[pn][k*ROWP + f0] = nq4;
        *(float4*)&xk_s[pn][k*ROWP + f0] = nk4;
        {
            float ss = nk4.x*nk4.x + nk4.y*nk4.y + nk4.z*nk4.z + nk4.w*nk4.w;
            #pragma unroll
            for (int m = 8; m >= 1; m >>= 1) ss += __shfl_xor_sync(~0u, ss, m, 16);
            if (q == 0) eta_s[pn][k] = 0.01f / (1.0f + fmaxf(sqrtf(ss), 1e-6f));
        }
        __syncthreads();                                   // S3

        q4 = nq4; k4 = nk4; v4 = nv4; p = pn;
    }
}

extern "C" void kernel_launch(void* const* d_in, const int* in_sizes, int n_in,
                              void* d_out, int out_size) {
    const float* XQ  = (const float*)d_in[0];
    const float* XK  = (const float*)d_in[1];
    const float* XV  = (const float*)d_in[2];
    const float* W1  = (const float*)d_in[3];
    const float* b1  = (const float*)d_in[4];
    const float* gam = (const float*)d_in[5];
    const float* bet = (const float*)d_in[6];
    float* out = (float*)d_out;

    const int nbh = in_sizes[0] / (TT * 16 * 64);   // B*H = 64
    ttt_kernel<<<nbh, NT>>>(XQ, XK, XV, W1, b1, gam, bet, out);
}